// round 15
// baseline (speedup 1.0000x reference)
#include <cuda_runtime.h>
#include <cuda_fp16.h>
#include <math.h>
#include <stdint.h>

// ---------------------------------------------------------------------------
// Scratch buffers (device globals; no allocation allowed)
// ---------------------------------------------------------------------------
#define MAX_L   5000
#define DIMM    1536
__device__ float  g_q[MAX_L * DIMM];
__device__ float  g_k[MAX_L * DIMM];
__device__ __half g_xh[MAX_L * DIMM];
__device__ __half g_qh[MAX_L * DIMM];
__device__ __half g_kh[MAX_L * DIMM];
__device__ __half g_vh[MAX_L * DIMM];
__device__ __half g_oh[MAX_L * DIMM];
__device__ __half g_wq[DIMM * DIMM];
__device__ __half g_wk[DIMM * DIMM];
__device__ __half g_wv[DIMM * DIMM];
__device__ __half g_wo[DIMM * DIMM];

// ---------------------------------------------------------------------------
// Helpers
// ---------------------------------------------------------------------------
__device__ __forceinline__ uint32_t packh2(float a, float b) {
    __half2 h = __floats2half2_rn(a, b);
    return *(uint32_t*)&h;
}

__device__ __forceinline__ void ldsm4h(uint32_t* r, const __half* p) {
    uint32_t a = (uint32_t)__cvta_generic_to_shared(p);
    asm volatile("ldmatrix.sync.aligned.m8n8.x4.shared.b16 {%0,%1,%2,%3}, [%4];"
                 : "=r"(r[0]), "=r"(r[1]), "=r"(r[2]), "=r"(r[3]) : "r"(a));
}

__device__ __forceinline__ void ldsm4t(uint32_t* r, const __half* p) {
    uint32_t a = (uint32_t)__cvta_generic_to_shared(p);
    asm volatile(
        "ldmatrix.sync.aligned.m8n8.x4.trans.shared.b16 {%0,%1,%2,%3}, [%4];"
        : "=r"(r[0]), "=r"(r[1]), "=r"(r[2]), "=r"(r[3]) : "r"(a));
}

__device__ __forceinline__ void mma_f16(float* d, const uint32_t* a,
                                        const uint32_t* b) {
    asm volatile(
        "mma.sync.aligned.m16n8k16.row.col.f32.f16.f16.f32 "
        "{%0,%1,%2,%3}, {%4,%5,%6,%7}, {%8,%9}, {%0,%1,%2,%3};"
        : "+f"(d[0]), "+f"(d[1]), "+f"(d[2]), "+f"(d[3])
        : "r"(a[0]), "r"(a[1]), "r"(a[2]), "r"(a[3]), "r"(b[0]), "r"(b[1]));
}

__device__ __forceinline__ void cpa16(uint32_t dst, const void* src, int sz) {
    asm volatile("cp.async.cg.shared.global [%0], [%1], 16, %2;"
                 :: "r"(dst), "l"(src), "r"(sz) : "memory");
}
__device__ __forceinline__ void cpa_commit() {
    asm volatile("cp.async.commit_group;" ::: "memory");
}

// ---------------------------------------------------------------------------
// Prep (single launch): z<4 -> weight transpose W[K][N] f32 -> Wt[N][K] f16;
// z==4 -> x f32 -> f16 (grid-stride).
// ---------------------------------------------------------------------------
__global__ __launch_bounds__(256) void prep_all(
    const float* __restrict__ W0, const float* __restrict__ W1,
    const float* __restrict__ W2, const float* __restrict__ W3,
    __half* __restrict__ T0, __half* __restrict__ T1,
    __half* __restrict__ T2, __half* __restrict__ T3,
    const float* __restrict__ x, __half* __restrict__ xh,
    int K, int N, int nx)
{
    if (blockIdx.z == 4) {
        int nb = gridDim.x * gridDim.y;
        int bid = blockIdx.y * gridDim.x + blockIdx.x;
        int stridei = nb * 256;
        for (int i = bid * 256 + threadIdx.x; i * 4 < nx; i += stridei) {
            float4 v = *(const float4*)(x + i * 4);
            uint2 t;
            t.x = packh2(v.x, v.y);
            t.y = packh2(v.z, v.w);
            *(uint2*)(xh + i * 4) = t;
        }
        return;
    }

    const float* W = (blockIdx.z == 0) ? W0 : (blockIdx.z == 1) ? W1
                   : (blockIdx.z == 2) ? W2 : W3;
    __half* Wt = (blockIdx.z == 0) ? T0 : (blockIdx.z == 1) ? T1
               : (blockIdx.z == 2) ? T2 : T3;

    __shared__ float t[32][33];
    const int tx = threadIdx.x & 31;
    const int ty = threadIdx.x >> 5;
    const int n0 = blockIdx.x << 5;
    const int k0 = blockIdx.y << 5;
#pragma unroll
    for (int i = 0; i < 4; i++)
        t[ty + 8 * i][tx] = W[(size_t)(k0 + ty + 8 * i) * N + n0 + tx];
    __syncthreads();
#pragma unroll
    for (int i = 0; i < 4; i++)
        Wt[(size_t)(n0 + ty + 8 * i) * K + k0 + tx] =
            __float2half_rn(t[tx][ty + 8 * i]);
}

// ---------------------------------------------------------------------------
// all-fp16 GEMM body: 128x128x32 tile, 8 warps, m16n8k16,
// cp.async ring-of-3 pipeline (1 syncthreads per slab, prefetch depth 2).
// Epilogue: HALF_OUT ? write __half : write float.
// ---------------------------------------------------------------------------
#define GLDH 40
#define GSTAGE (128 * GLDH)   // halves per operand per stage

template<bool HALF_OUT>
__device__ __forceinline__ void gemm_body(
    const __half* __restrict__ A, const __half* __restrict__ Wt,
    const float* __restrict__ bias, void* __restrict__ Cv,
    int M, int N, int K, __half* smh)
{
    const int tid = threadIdx.x;
    const int wid = tid >> 5;
    const int lane = tid & 31;
    const int wm = wid >> 2;
    const int wn = wid & 3;
    const int m0 = blockIdx.y << 7;
    const int n0 = blockIdx.x << 7;

    const int lrA = (lane & 7) + ((lane >> 3) & 1) * 8;
    const int lcA = (lane >> 4) * 8;
    const int lrB = (lane & 7) + ((lane >> 4) << 3);
    const int lcB = ((lane >> 3) & 1) * 8;

    const uint32_t smb = (uint32_t)__cvta_generic_to_shared(smh);

    float acc[4][4][4];
#pragma unroll
    for (int mt = 0; mt < 4; mt++)
#pragma unroll
        for (int nt = 0; nt < 4; nt++)
#pragma unroll
            for (int i = 0; i < 4; i++) acc[mt][nt][i] = 0.f;

    const int NS = K >> 5;

    auto stage = [&](int s) {
        const int buf = s % 3;
        const int k0 = s << 5;
        const uint32_t ab = smb + buf * (2 * GSTAGE) * 2;
        const uint32_t bb = ab + GSTAGE * 2;
#pragma unroll
        for (int it = 0; it < 2; it++) {
            int idx = tid + it * 256;          // 0..511
            int row = idx >> 2;
            int ch = idx & 3;
            uint32_t so = (uint32_t)(row * GLDH + ch * 8) * 2;
            int gr = m0 + row;
            int sz = (gr < M) ? 16 : 0;
            cpa16(ab + so, A + (size_t)gr * K + k0 + ch * 8, sz);
            cpa16(bb + so, Wt + (size_t)(n0 + row) * K + k0 + ch * 8, 16);
        }
        cpa_commit();
    };

    stage(0);
    if (NS > 1) stage(1);

    for (int s = 0; s < NS; s++) {
        if (s + 1 < NS)
            asm volatile("cp.async.wait_group 1;" ::: "memory");
        else
            asm volatile("cp.async.wait_group 0;" ::: "memory");
        __syncthreads();
        if (s + 2 < NS) stage(s + 2);

        const __half* Ab = smh + (s % 3) * (2 * GSTAGE);
        const __half* Bb = Ab + GSTAGE;
#pragma unroll
        for (int ks = 0; ks < 2; ks++) {
            uint32_t af[4][4], bf[2][4];
#pragma unroll
            for (int mt = 0; mt < 4; mt++)
                ldsm4h(af[mt], &Ab[(wm * 64 + mt * 16 + lrA) * GLDH + ks * 16 + lcA]);
#pragma unroll
            for (int np = 0; np < 2; np++)
                ldsm4h(bf[np], &Bb[(wn * 32 + np * 16 + lrB) * GLDH + ks * 16 + lcB]);
#pragma unroll
            for (int mt = 0; mt < 4; mt++)
#pragma unroll
                for (int nt = 0; nt < 4; nt++)
                    mma_f16(acc[mt][nt], af[mt], &bf[nt >> 1][(nt & 1) * 2]);
        }
    }

    const int q = lane & 3;
    const int rb = lane >> 2;
#pragma unroll
    for (int nt = 0; nt < 4; nt++) {
        int col = n0 + wn * 32 + nt * 8 + q * 2;
        float2 bv = *(const float2*)(bias + col);
#pragma unroll
        for (int mt = 0; mt < 4; mt++) {
            int r = m0 + wm * 64 + mt * 16 + rb;
            if (r < M) {
                if (HALF_OUT)
                    *(uint32_t*)((__half*)Cv + (size_t)r * N + col) =
                        packh2(acc[mt][nt][0] + bv.x, acc[mt][nt][1] + bv.y);
                else
                    *(float2*)((float*)Cv + (size_t)r * N + col) =
                        make_float2(acc[mt][nt][0] + bv.x, acc[mt][nt][1] + bv.y);
            }
            if (r + 8 < M) {
                if (HALF_OUT)
                    *(uint32_t*)((__half*)Cv + (size_t)(r + 8) * N + col) =
                        packh2(acc[mt][nt][2] + bv.x, acc[mt][nt][3] + bv.y);
                else
                    *(float2*)((float*)Cv + (size_t)(r + 8) * N + col) =
                        make_float2(acc[mt][nt][2] + bv.x, acc[mt][nt][3] + bv.y);
            }
        }
    }
}

// Fused QKV GEMM: z=0 -> q (f32), z=1 -> k (f32), z=2 -> v (half, direct)
__global__ __launch_bounds__(256, 2) void qkv_gemm(
    const __half* __restrict__ A,
    const __half* __restrict__ wq, const __half* __restrict__ wk,
    const __half* __restrict__ wv,
    const float* __restrict__ bq, const float* __restrict__ bk,
    const float* __restrict__ bv,
    float* __restrict__ q, float* __restrict__ k, __half* __restrict__ vh,
    int M, int N, int K)
{
    extern __shared__ __align__(16) __half gsm[];
    if (blockIdx.z == 0)
        gemm_body<false>(A, wq, bq, q, M, N, K, gsm);
    else if (blockIdx.z == 1)
        gemm_body<false>(A, wk, bk, k, M, N, K, gsm);
    else
        gemm_body<true>(A, wv, bv, vh, M, N, K, gsm);
}

__global__ __launch_bounds__(256, 2) void out_gemm(
    const __half* __restrict__ A, const __half* __restrict__ Wt,
    const float* __restrict__ bias, float* __restrict__ C,
    int M, int N, int K)
{
    extern __shared__ __align__(16) __half gsm[];
    gemm_body<false>(A, Wt, bias, C, M, N, K, gsm);
}

// ---------------------------------------------------------------------------
// Fused post-QKV: z=0 rms+rope(q), z=1 rms+rope(k). One block per row.
// ---------------------------------------------------------------------------
__global__ __launch_bounds__(256) void qkv_post(
    const float* __restrict__ q, const float* __restrict__ k,
    __half* __restrict__ qh, __half* __restrict__ kh,
    const float* __restrict__ gq, const float* __restrict__ gk,
    const float* __restrict__ freqs, const int* __restrict__ grid_sizes,
    int L, int dim, int c, int c0, int c1)
{
    const int z = blockIdx.y;
    const int l = blockIdx.x;

    const float* row = ((z == 0) ? q : k) + (size_t)l * dim;
    __half* rowh = ((z == 0) ? qh : kh) + (size_t)l * dim;
    const float* g = (z == 0) ? gq : gk;

    float s = 0.f;
    for (int i = threadIdx.x; i < dim; i += blockDim.x) {
        float vv = row[i];
        s += vv * vv;
    }
#pragma unroll
    for (int off = 16; off; off >>= 1)
        s += __shfl_down_sync(0xffffffffu, s, off);

    __shared__ float red[9];
    int warp = threadIdx.x >> 5, lane = threadIdx.x & 31;
    if (lane == 0) red[warp] = s;
    __syncthreads();
    if (threadIdx.x == 0) {
        float t = 0.f;
        for (int i = 0; i < 8; i++) t += red[i];
        red[8] = t;
    }
    __syncthreads();
    const float rs = rsqrtf(red[8] / (float)dim + 1e-6f);

    const int gf = grid_sizes[0], gh = grid_sizes[1], gw = grid_sizes[2];
    const int sl = gf * gh * gw;
    const bool rot = (l < sl);
    int fi = 0, hi = 0, wi = 0;
    if (rot) {
        fi = l / (gh * gw);
        int rem = l - fi * gh * gw;
        hi = rem / gw;
        wi = rem - hi * gw;
    }

    const int half = dim >> 1;
    for (int p = threadIdx.x; p < half; p += blockDim.x) {
        int head = p / c;
        int j = p - head * c;
        int i0 = head * 2 * c + 2 * j;
        float a = row[i0] * rs * g[i0];
        float b = row[i0 + 1] * rs * g[i0 + 1];
        float o0 = a, o1 = b;
        if (rot) {
            int pos = (j < c0) ? fi : ((j < c0 + c1) ? hi : wi);
            float ang = freqs[pos * c + j];
            float sn, cs;
            sincosf(ang, &sn, &cs);
            o0 = a * cs - b * sn;
            o1 = a * sn + b * cs;
        }
        *(__half2*)(rowh + i0) = __floats2half2_rn(o0, o1);
    }
}

// ---------------------------------------------------------------------------
// fp16 flash attention: 128 q rows x 1 head per CTA, 8 warps.
// Ring-of-3 cp.async K/V tiles (1 sync per tile, prefetch depth 2);
// ldmatrix.trans for V; exp2 softmax with warp-voted rescale skip.
// ---------------------------------------------------------------------------
#define LDK 136

__global__ __launch_bounds__(256) void attn_f16(
    const __half* __restrict__ qg, const __half* __restrict__ kg,
    const __half* __restrict__ vg, __half* __restrict__ og,
    int L, int nh, const int* __restrict__ seq_lens)
{
    extern __shared__ __align__(16) __half smh[];
    // layout: K0 K1 K2 V0 V1 V2, each 64*LDK halves. Q staged via K0..K1.

    const int tid = threadIdx.x;
    const int wid = tid >> 5;
    const int lane = tid & 31;
    const int q = lane & 3;
    const int rb = lane >> 2;
    const int head = blockIdx.y;
    const int q0 = blockIdx.x << 7;
    const int hoff = head * 128;
    const size_t stride = (size_t)nh * 128;
    const int seqlen = seq_lens[0];
    const float scale2 = rsqrtf(128.0f) * 1.4426950408889634f;

    const int lrA = (lane & 7) + ((lane >> 3) & 1) * 8;
    const int lcA = (lane >> 4) * 8;
    const int lrB = (lane & 7) + ((lane >> 4) << 3);
    const int lcB = ((lane >> 3) & 1) * 8;
    const int trow = lane & 15;
    const int tcol = (lane >> 4) << 3;

    const uint32_t smb = (uint32_t)__cvta_generic_to_shared(smh);
    const uint32_t TILE = 64 * LDK * 2;   // bytes per buffer

    const int nkt = (seqlen + 63) >> 6;

    auto stage_kv = [&](int t) {
        const int buf = t % 3;
        const int kbase = t << 6;
        const uint32_t kb = smb + buf * TILE;
        const uint32_t vb = smb + (3 + buf) * TILE;
#pragma unroll
        for (int it = 0; it < 4; it++) {
            int idx = tid + it * 256;
            int row = idx >> 4;
            int ch = idx & 15;
            int gr = kbase + row;
            int sz = (gr < L) ? 16 : 0;
            size_t goff = (size_t)gr * stride + hoff + ch * 8;
            uint32_t so = (uint32_t)(row * LDK + ch * 8) * 2;
            cpa16(kb + so, kg + goff, sz);
            cpa16(vb + so, vg + goff, sz);
        }
        cpa_commit();
    };

    // ---- stage Q (128 rows) through K0..K1, read Q fragments ----
#pragma unroll
    for (int it = 0; it < 8; it++) {
        int idx = tid + it * 256;
        int row = idx >> 4;
        int ch = idx & 15;
        int gr = q0 + row;
        int sz = (gr < L) ? 16 : 0;
        cpa16(smb + (uint32_t)(row * LDK + ch * 8) * 2,
              qg + (size_t)gr * stride + hoff + ch * 8, sz);
    }
    cpa_commit();
    asm volatile("cp.async.wait_group 0;" ::: "memory");
    __syncthreads();

    uint32_t qf[8][4];
#pragma unroll
    for (int ks = 0; ks < 8; ks++)
        ldsm4h(qf[ks], &smh[(wid * 16 + lrA) * LDK + ks * 16 + lcA]);
    __syncthreads();

    float o[16][4];
#pragma unroll
    for (int nt = 0; nt < 16; nt++)
#pragma unroll
        for (int i = 0; i < 4; i++) o[nt][i] = 0.f;
    float m_r[2] = {-1e30f, -1e30f};
    float l_r[2] = {0.f, 0.f};

    stage_kv(0);
    if (nkt > 1) stage_kv(1);

    for (int t = 0; t < nkt; t++) {
        const int buf = t % 3;
        const int kbase = t << 6;
        const __half* Ks = smh + buf * (64 * LDK);
        const __half* Vs = smh + (3 + buf) * (64 * LDK);

        if (t + 1 < nkt)
            asm volatile("cp.async.wait_group 1;" ::: "memory");
        else
            asm volatile("cp.async.wait_group 0;" ::: "memory");
        __syncthreads();
        if (t + 2 < nkt) stage_kv(t + 2);

        // ---- S = Q K^T ----
        float s[8][4];
#pragma unroll
        for (int nt = 0; nt < 8; nt++)
#pragma unroll
            for (int i = 0; i < 4; i++) s[nt][i] = 0.f;

#pragma unroll
        for (int ks = 0; ks < 8; ks++) {
#pragma unroll
            for (int np = 0; np < 4; np++) {
                uint32_t bf[4];
                ldsm4h(bf, &Ks[(np * 16 + lrB) * LDK + ks * 16 + lcB]);
                mma_f16(s[2 * np], qf[ks], bf);
                mma_f16(s[2 * np + 1], qf[ks], bf + 2);
            }
        }

        // ---- scale (base-2) + mask ----
#pragma unroll
        for (int nt = 0; nt < 8; nt++) {
            int col = kbase + nt * 8 + 2 * q;
            s[nt][0] = (col     < seqlen) ? s[nt][0] * scale2 : -1e30f;
            s[nt][2] = (col     < seqlen) ? s[nt][2] * scale2 : -1e30f;
            s[nt][1] = (col + 1 < seqlen) ? s[nt][1] * scale2 : -1e30f;
            s[nt][3] = (col + 1 < seqlen) ? s[nt][3] * scale2 : -1e30f;
        }

        // ---- online softmax (base 2) with rescale skip ----
#pragma unroll
        for (int r = 0; r < 2; r++) {
            float mx = -1e30f;
#pragma unroll
            for (int nt = 0; nt < 8; nt++)
                mx = fmaxf(mx, fmaxf(s[nt][2 * r], s[nt][2 * r + 1]));
            mx = fmaxf(mx, __shfl_xor_sync(0xffffffffu, mx, 1));
            mx = fmaxf(mx, __shfl_xor_sync(0xffffffffu, mx, 2));
            bool upd = (mx > m_r[r]);
            float mn = upd ? mx : m_r[r];
            float cf = upd ? exp2f(m_r[r] - mn) : 1.0f;
            m_r[r] = mn;
            float sum = 0.f;
#pragma unroll
            for (int nt = 0; nt < 8; nt++) {
                float p0 = exp2f(s[nt][2 * r] - mn);
                float p1 = exp2f(s[nt][2 * r + 1] - mn);
                s[nt][2 * r] = p0;
                s[nt][2 * r + 1] = p1;
                sum += p0 + p1;
            }
            sum += __shfl_xor_sync(0xffffffffu, sum, 1);
            sum += __shfl_xor_sync(0xffffffffu, sum, 2);
            l_r[r] = l_r[r] * cf + sum;
            if (__any_sync(0xffffffffu, upd)) {
#pragma unroll
                for (int nt = 0; nt < 16; nt++) {
                    o[nt][2 * r] *= cf;
                    o[nt][2 * r + 1] *= cf;
                }
            }
        }

        // ---- O += P V ----
#pragma unroll
        for (int kt = 0; kt < 4; kt++) {
            uint32_t aP[4];
            aP[0] = packh2(s[2 * kt][0], s[2 * kt][1]);
            aP[1] = packh2(s[2 * kt][2], s[2 * kt][3]);
            aP[2] = packh2(s[2 * kt + 1][0], s[2 * kt + 1][1]);
            aP[3] = packh2(s[2 * kt + 1][2], s[2 * kt + 1][3]);
            const __half* vrow = &Vs[(kt * 16 + trow) * LDK + tcol];
#pragma unroll
            for (int np = 0; np < 8; np++) {
                uint32_t bf[4];
                ldsm4t(bf, vrow + np * 16);
                mma_f16(o[2 * np], aP, bf);
                mma_f16(o[2 * np + 1], aP, bf + 2);
            }
        }
    }

    // ---- normalize + store (fp16) ----
    float inv0 = 1.0f / l_r[0];
    float inv1 = 1.0f / l_r[1];
    int r = q0 + wid * 16 + rb;
#pragma unroll
    for (int nt = 0; nt < 16; nt++) {
        int col = hoff + nt * 8 + 2 * q;
        if (r < L)
            *(__half2*)(og + (size_t)r * stride + col) =
                __floats2half2_rn(o[nt][0] * inv0, o[nt][1] * inv0);
        if (r + 8 < L)
            *(__half2*)(og + (size_t)(r + 8) * stride + col) =
                __floats2half2_rn(o[nt][2] * inv1, o[nt][3] * inv1);
    }
}

// ---------------------------------------------------------------------------
// kernel_launch — attn_f16 sits at 0-based launch index 3 (profiled slot).
// ---------------------------------------------------------------------------
extern "C" void kernel_launch(void* const* d_in, const int* in_sizes, int n_in,
                              void* d_out, int out_size)
{
    (void)n_in; (void)out_size;
    const float* x          = (const float*)d_in[0];
    const int*   seq_lens   = (const int*)d_in[1];
    const int*   grid_sizes = (const int*)d_in[2];
    const float* freqs      = (const float*)d_in[3];
    const float* Wq = (const float*)d_in[4];
    const float* bq = (const float*)d_in[5];
    const float* Wk = (const float*)d_in[6];
    const float* bk = (const float*)d_in[7];
    const float* Wv = (const float*)d_in[8];
    const float* bv = (const float*)d_in[9];
    const float* Wo = (const float*)d_in[10];
    const float* bo = (const float*)d_in[11];
    const float* gq = (const float*)d_in[12];
    const float* gk = (const float*)d_in[13];
    float* out = (float*)d_out;

    const int dim = in_sizes[5];             // 1536
    const int L   = in_sizes[0] / dim;       // 5000
    const int c   = in_sizes[3] / 1024;      // 64
    const int d   = 2 * c;                   // 128
    const int nh  = dim / d;                 // 12
    const int c1  = c / 3;                   // 21
    const int c0  = c - 2 * c1;              // 22

    float *qp, *kp;
    __half *xh, *qh, *kh, *vh, *oh, *wqt, *wkt, *wvt, *wot;
    cudaGetSymbolAddress((void**)&qp, g_q);
    cudaGetSymbolAddress((void**)&kp, g_k);
    cudaGetSymbolAddress((void**)&xh, g_xh);
    cudaGetSymbolAddress((void**)&qh, g_qh);
    cudaGetSymbolAddress((void**)&kh, g_kh);
    cudaGetSymbolAddress((void**)&vh, g_vh);
    cudaGetSymbolAddress((void**)&oh, g_oh);
    cudaGetSymbolAddress((void**)&wqt, g_wq);
    cudaGetSymbolAddress((void**)&wkt, g_wk);
    cudaGetSymbolAddress((void**)&wvt, g_wv);
    cudaGetSymbolAddress((void**)&wot, g_wo);

    const int gemm_smem = 3 * 2 * GSTAGE * (int)sizeof(__half);  // 61440
    cudaFuncSetAttribute(qkv_gemm, cudaFuncAttributeMaxDynamicSharedMemorySize,
                         gemm_smem);
    cudaFuncSetAttribute(out_gemm, cudaFuncAttributeMaxDynamicSharedMemorySize,
                         gemm_smem);
    const int attn_smem = 6 * 64 * LDK * (int)sizeof(__half);    // 104448
    cudaFuncSetAttribute(attn_f16, cudaFuncAttributeMaxDynamicSharedMemorySize,
                         attn_smem);

    // 0: prep (weight transposes + x->half)
    dim3 tgrid(dim / 32, dim / 32, 5);
    prep_all<<<tgrid, 256>>>(Wq, Wk, Wv, Wo, wqt, wkt, wvt, wot,
                             x, xh, dim, dim, L * dim);

    // 1: fused QKV GEMM (v written as half directly)
    dim3 gblk(dim / 128, (L + 127) / 128, 3);
    qkv_gemm<<<gblk, 256, gemm_smem>>>(xh, wqt, wkt, wvt, bq, bk, bv,
                                       qp, kp, vh, L, dim, dim);

    // 2: fused post (rms+rope q/k)
    dim3 pgrid(L, 2);
    qkv_post<<<pgrid, 256>>>(qp, kp, qh, kh, gq, gk, freqs,
                             grid_sizes, L, dim, c, c0, c1);

    // 3: attention (profiled slot)
    dim3 fgrid((L + 127) / 128, nh);
    attn_f16<<<fgrid, 256, attn_smem>>>(qh, kh, vh, oh, L, nh, seq_lens);

    // 4: output projection
    dim3 oblk(dim / 128, (L + 127) / 128);
    out_gemm<<<oblk, 256, gemm_smem>>>(oh, wot, bo, out, L, dim, dim);
}